// round 12
// baseline (speedup 1.0000x reference)
#include <cuda_runtime.h>
#include <cuda_fp16.h>
#include <cstdint>

#define BATCH   2
#define LSEQ    2048
#define DM      512
#define NM      32
#define NMH     16          // modes per thread (half)
#define NLAYER  4
#define VOCAB   50257
#define NC      64          // chunks
#define TCH     32          // chunk length = LSEQ/NC
#define D2      (2*DM)
#define MROWS   (BATCH*LSEQ)   // 4096

// ---------------- scratch (device globals; no mallocs allowed) ----------------
__device__ float  g_x   [MROWS*DM];       // residual stream (fp32)
__device__ __half g_yh  [MROWS*DM];       // gelu(conv+skip) output (fp16, GEMM A)
__device__ __half g_xh  [MROWS*DM];       // layernorm output (fp16, GEMM A)
__device__ float  g_sre [BATCH*NC*NM*DM];
__device__ float  g_sim [BATCH*NC*NM*DM];
__device__ float  g_abr [NLAYER*NM*DM];
__device__ float  g_abi [NLAYER*NM*DM];
__device__ float  g_ctr [NLAYER*NM*DM];
__device__ float  g_cti [NLAYER*NM*DM];
__device__ __half g_wph [NLAYER*D2*DM];   // proj weights fp16 (GLU-interleaved rows)
__device__ __half g_hwh [(size_t)VOCAB*DM]; // head weights fp16
__device__ int    g_is64;

// ---------------- input_ids dtype sniffing (int32 vs int64) ----------------
__global__ void k_detect(const int* __restrict__ ids) {
    __shared__ int s_any;
    if (threadIdx.x == 0) s_any = 0;
    __syncthreads();
    int any = 0;
    for (int i = threadIdx.x; i < MROWS/2; i += blockDim.x) any |= ids[2*i + 1];
    if (any) atomicOr(&s_any, 1);
    __syncthreads();
    if (threadIdx.x == 0) g_is64 = (s_any == 0) ? 1 : 0;
}

// ---------------- embedding ----------------
__global__ void k_embed(const int* __restrict__ ids,
                        const float* __restrict__ tok,
                        const float* __restrict__ pos) {
    int idx = blockIdx.x * blockDim.x + threadIdx.x;
    if (idx >= MROWS*DM) return;
    int m = idx / DM, d = idx % DM;
    int l = m % LSEQ;
    int t;
    if (g_is64) t = (int)((const long long*)ids)[m];
    else        t = ids[m];
    g_x[idx] = tok[(size_t)t*DM + d] + pos[l*DM + d];
}

// ---------------- fp32 -> fp16 weight conversion ----------------
__global__ void k_cvt(const float* __restrict__ src, __half* __restrict__ dst, int n4) {
    int i = blockIdx.x * blockDim.x + threadIdx.x;
    if (i >= n4) return;
    float4 v = reinterpret_cast<const float4*>(src)[i];
    reinterpret_cast<__half2*>(dst)[2*i]   = __floats2half2_rn(v.x, v.y);
    reinterpret_cast<__half2*>(dst)[2*i+1] = __floats2half2_rn(v.z, v.w);
}

// proj weights: interleave GLU halves — dst row 2d = src row d, dst row 2d+1 = src row d+512
__global__ void k_cvt_proj(const float* __restrict__ src, __half* __restrict__ dst, int n4) {
    int i = blockIdx.x * blockDim.x + threadIdx.x;   // chunk of 4 floats
    if (i >= n4) return;                             // n4 = NLAYER*D2*(DM/4)
    int k4    = i & 127;                             // DM/4 = 128
    int rem   = i >> 7;
    int row   = rem & (D2 - 1);                      // 0..1023
    int layer = rem >> 10;
    int nrow  = 2*(row & (DM-1)) + (row >> 9);       // interleave
    float4 v = reinterpret_cast<const float4*>(src)[i];
    size_t o = ((size_t)layer*D2 + nrow)*128 + k4;
    reinterpret_cast<__half2*>(dst)[2*o]   = __floats2half2_rn(v.x, v.y);
    reinterpret_cast<__half2*>(dst)[2*o+1] = __floats2half2_rn(v.z, v.w);
}

// ---------------- S4D discretized coefficients (ALL layers upfront) ----------------
__global__ void k_coeff(const float* __restrict__ log_dt,
                        const float* __restrict__ C_re,
                        const float* __restrict__ C_im) {
    int idx = blockIdx.x * blockDim.x + threadIdx.x;   // layer*NM*DM + n*DM + d
    if (idx >= NLAYER*NM*DM) return;
    int d     = idx % DM;
    int n     = (idx / DM) % NM;
    int layer = idx / (NM*DM);
    float dt  = expf(log_dt[layer*DM + d]);
    const float PI = 3.14159265358979f;
    float aim = PI * (float)n;                         // A = -0.5 + i*pi*n
    float xr = -0.5f * dt, xi = aim * dt;
    float e  = expf(xr);
    float abr = e * cosf(xi), abi = e * sinf(xi);      // abar = exp(dt*A)
    float cr = C_re[(layer*DM + d)*NM + n];
    float ci = C_im[(layer*DM + d)*NM + n];
    float emr = abr - 1.0f, emi = abi;                 // exp(dtA)-1
    float nr = cr*emr - ci*emi;
    float ni = cr*emi + ci*emr;
    float inv = 2.0f / (0.25f + aim*aim);
    g_abr[idx] = abr;  g_abi[idx] = abi;
    g_ctr[idx] = (nr*(-0.5f) + ni*aim) * inv;
    g_cti[idx] = (ni*(-0.5f) - nr*aim) * inv;
}

// ---------------- chunk-local end states S_c (16 modes/thread, 256 thr) ----------------
__global__ void __launch_bounds__(256, 3) k_chunk(int layer) {
    int blk = blockIdx.x;                     // b*NC*4 + c*4 + g4
    int g4  = blk & 3;
    int c   = (blk >> 2) % NC;
    int b   = blk / (NC*4);
    int dl  = threadIdx.x & 127;
    int nb  = (threadIdx.x >> 7) * NMH;       // mode base: 0 or 16
    int d   = g4*128 + dl;
    int co  = layer*NM*DM;

    float ar[NMH], ai[NMH], sr[NMH], si[NMH];
#pragma unroll
    for (int n = 0; n < NMH; n++) {
        ar[n] = g_abr[co + (nb+n)*DM + d]; ai[n] = g_abi[co + (nb+n)*DM + d];
        sr[n] = 0.f; si[n] = 0.f;
    }
    const float* xp = g_x + ((size_t)b*LSEQ + c*TCH)*DM + d;

    auto step = [&](float u) {
#pragma unroll
        for (int n = 0; n < NMH; n++) {
            float nsr = fmaf(ar[n], sr[n], fmaf(-ai[n], si[n], u));
            float nsi = fmaf(ar[n], si[n], ai[n]*sr[n]);
            sr[n] = nsr; si[n] = nsi;
        }
    };
    for (int t0 = 0; t0 < TCH; t0 += 4) {       // staged loads: MLP=4
        float u0 = xp[(size_t)(t0+0)*DM];
        float u1 = xp[(size_t)(t0+1)*DM];
        float u2 = xp[(size_t)(t0+2)*DM];
        float u3 = xp[(size_t)(t0+3)*DM];
        step(u0); step(u1); step(u2); step(u3);
    }
    size_t off = ((size_t)(b*NC + c)*NM + nb)*DM + d;
#pragma unroll
    for (int n = 0; n < NMH; n++) {
        g_sre[off + (size_t)n*DM] = sr[n];
        g_sim[off + (size_t)n*DM] = si[n];
    }
}

// ---------------- sequential scan over chunks: S_c -> E_c (prefetched) ----------------
__global__ void k_scan(int layer) {
    int idx = blockIdx.x * blockDim.x + threadIdx.x;
    if (idx >= BATCH*NM*DM) return;
    int d = idx % DM;
    int n = (idx / DM) % NM;
    int b = idx / (NM*DM);
    int co = layer*NM*DM;
    float pr = g_abr[co + n*DM + d], pi = g_abi[co + n*DM + d];
#pragma unroll
    for (int s = 0; s < 5; s++) {              // abar^(2^5) = abar^TCH
        float t = pr*pr - pi*pi; pi = 2.f*pr*pi; pr = t;
    }
    float er = 0.f, ei = 0.f;
    size_t off = ((size_t)(b*NC)*NM + n)*DM + d;
    const size_t stride = (size_t)NM*DM;
    float Sr = g_sre[off], Si = g_sim[off];
    for (int c = 0; c < NC; c++) {
        size_t offn = off + stride;
        float Sr2 = 0.f, Si2 = 0.f;
        if (c + 1 < NC) { Sr2 = g_sre[offn]; Si2 = g_sim[offn]; }  // prefetch
        g_sre[off] = er; g_sim[off] = ei;      // store carry-in E_c
        float ner = fmaf(pr, er, fmaf(-pi, ei, Sr));
        float nei = fmaf(pr, ei, fmaf( pi, er, Si));
        er = ner; ei = nei;
        Sr = Sr2; Si = Si2; off = offn;
    }
}

// ---------------- conv + skip + gelu -> fp16 (16 modes/thread, smem combine) ----------------
__global__ void __launch_bounds__(256, 2) k_conv(const float* __restrict__ skipD, int layer) {
    __shared__ float part[2][TCH][128];
    int blk = blockIdx.x;
    int g4  = blk & 3;
    int c   = (blk >> 2) % NC;
    int b   = blk / (NC*4);
    int dl  = threadIdx.x & 127;
    int h   = threadIdx.x >> 7;               // mode half
    int nb  = h * NMH;
    int d   = g4*128 + dl;
    int co  = layer*NM*DM;

    float ar[NMH], ai[NMH], cr[NMH], ci[NMH], sr[NMH], si[NMH];
    size_t soff = ((size_t)(b*NC + c)*NM + nb)*DM + d;
#pragma unroll
    for (int n = 0; n < NMH; n++) {
        ar[n] = g_abr[co + (nb+n)*DM + d]; ai[n] = g_abi[co + (nb+n)*DM + d];
        cr[n] = g_ctr[co + (nb+n)*DM + d]; ci[n] = g_cti[co + (nb+n)*DM + d];
        sr[n] = g_sre[soff + (size_t)n*DM];
        si[n] = g_sim[soff + (size_t)n*DM];
    }
    const float* xp = g_x + ((size_t)b*LSEQ + c*TCH)*DM + d;

    auto step = [&](float u) -> float {
        float acc = 0.f;
#pragma unroll
        for (int n = 0; n < NMH; n++) {
            float nsr = fmaf(ar[n], sr[n], fmaf(-ai[n], si[n], u));
            float nsi = fmaf(ar[n], si[n], ai[n]*sr[n]);
            sr[n] = nsr; si[n] = nsi;
            acc = fmaf(cr[n], sr[n], acc);
            acc = fmaf(-ci[n], si[n], acc);
        }
        return acc;
    };
    for (int t0 = 0; t0 < TCH; t0 += 4) {       // staged loads: MLP=4
        float u0 = xp[(size_t)(t0+0)*DM];
        float u1 = xp[(size_t)(t0+1)*DM];
        float u2 = xp[(size_t)(t0+2)*DM];
        float u3 = xp[(size_t)(t0+3)*DM];
        part[h][t0+0][dl] = step(u0);
        part[h][t0+1][dl] = step(u1);
        part[h][t0+2][dl] = step(u2);
        part[h][t0+3][dl] = step(u3);
    }
    __syncthreads();

    // finish: 256 threads cover 32t x 128d; skip + gelu + fp16 store
    const float* xb = g_x  + ((size_t)b*LSEQ + c*TCH)*DM + g4*128;
    __half*      yb = g_yh + ((size_t)b*LSEQ + c*TCH)*DM + g4*128;
    for (int i = threadIdx.x; i < TCH*128; i += 256) {
        int t  = i >> 7;
        int dd = i & 127;
        float u  = xb[(size_t)t*DM + dd];
        float sk = skipD[layer*DM + g4*128 + dd];
        float yv = part[0][t][dd] + part[1][t][dd] + sk*u;
        float inner = 0.7978845608028654f * fmaf(0.044715f*yv, yv*yv, yv);
        float gv = 0.5f * yv * (1.f + tanhf(inner));
        yb[(size_t)t*DM + dd] = __float2half_rn(gv);
    }
}

// ---------------- fp16 tensor-core GEMM (m16n8k16, fp32 accum, ldmatrix) ----------------
// C[M,N] = A[M,K] * B[N,K]^T.  128x128 tile, BK=64, 3-stage cp.async,
// SINGLE __syncthreads per K-slab (cutlass-style), 8 warps (4m x 2n), warp 32x64.
// MODE 0: plain fp32 store to C.   MODE 1: fused GLU (interleaved B) += into g_x.
#define HLDA 72       // smem leading dim in halves (144B stride; 16B-aligned; LDSM conflict-free)
#define STG_H (128*HLDA)             // halves per matrix per stage
#define SMEM_GEMM (3*STG_H*2*2)      // 3 stages x (A+B) x 2B = 110592

template<int MODE>
__global__ void __launch_bounds__(256, 2) gemm_fp16(
    const __half* __restrict__ A, const __half* __restrict__ Bw,
    const float* __restrict__ bias, float* __restrict__ C,
    int M, int N, int K)
{
    extern __shared__ __half hs[];
    __half* As = hs;              // [3][128*HLDA]
    __half* Bs = hs + 3*STG_H;    // [3][128*HLDA]

    const int tid  = threadIdx.x;
    const int m0   = blockIdx.y * 128;
    const int n0   = blockIdx.x * 128;
    const int warp = tid >> 5, lane = tid & 31;
    const int wm = warp & 3;             // row-warp: wm*32
    const int wn = warp >> 2;            // col-warp: wn*64
    const int g  = lane >> 2;            // 0..7
    const int tg = lane & 3;             // 0..3

    float acc[2][8][4];
#pragma unroll
    for (int i = 0; i < 2; i++)
#pragma unroll
        for (int j = 0; j < 8; j++)
#pragma unroll
            for (int r = 0; r < 4; r++) acc[i][j][r] = 0.f;

    const int lrow = tid >> 1;
    const int lch  = (tid & 1) * 4;     // 16B chunk base (8 chunks per 128B row)

    const __half* Abase = A  + (size_t)m0 * K + lch*8;
    const __half* Bbase = Bw + lch*8;

    const int T = K / 64;               // 8 for K=512

    auto issue = [&](int t, int buf) {
        const __half* Ap = Abase + t*64 + (size_t)lrow * K;
        uint32_t da = (uint32_t)__cvta_generic_to_shared(
                          As + buf*STG_H + lrow*HLDA + lch*8);
#pragma unroll
        for (int c = 0; c < 4; c++)
            asm volatile("cp.async.ca.shared.global [%0], [%1], 16;\n"
                         :: "r"(da + c*16), "l"(Ap + c*8));
        int gr = n0 + lrow;
        const __half* Bp = Bbase + t*64 + (size_t)gr * K;
        uint32_t db = (uint32_t)__cvta_generic_to_shared(
                          Bs + buf*STG_H + lrow*HLDA + lch*8);
        int sz = (gr < N) ? 16 : 0;     // zero-fill OOB rows
#pragma unroll
        for (int c = 0; c < 4; c++)
            asm volatile("cp.async.ca.shared.global [%0], [%1], 16, %2;\n"
                         :: "r"(db + c*16), "l"(Bp + c*8), "r"(sz));
        asm volatile("cp.async.commit_group;\n");
    };

    // ldmatrix lane addressing: lanes 0-15 rows 0-15 @k, lanes 16-31 rows 0-15 @k+8
    const int lm_row = lane & 15;
    const int lm_k   = (lane >> 4) << 3;

    auto compute = [&](int buf) {
        uint32_t abase = (uint32_t)__cvta_generic_to_shared(
            As + buf*STG_H + (wm*32 + lm_row)*HLDA + lm_k);
        uint32_t bbase = (uint32_t)__cvta_generic_to_shared(
            Bs + buf*STG_H + (wn*64 + lm_row)*HLDA + lm_k);
#pragma unroll
        for (int kk = 0; kk < 64; kk += 16) {
            uint32_t af[2][4], bf[8][2];
#pragma unroll
            for (int mf = 0; mf < 2; mf++) {
                uint32_t ad = abase + (mf*16*HLDA + kk)*2;
                asm volatile("ldmatrix.sync.aligned.m8n8.x4.shared.b16 {%0,%1,%2,%3}, [%4];"
                             : "=r"(af[mf][0]), "=r"(af[mf][1]),
                               "=r"(af[mf][2]), "=r"(af[mf][3]) : "r"(ad));
            }
#pragma unroll
            for (int np = 0; np < 4; np++) {
                uint32_t bd = bbase + (np*16*HLDA + kk)*2;
                uint32_t b0, b1, b2, b3;
                asm volatile("ldmatrix.sync.aligned.m8n8.x4.shared.b16 {%0,%1,%2,%3}, [%4];"
                             : "=r"(b0), "=r"(b1), "=r"(b2), "=r"(b3) : "r"(bd));
                bf[2*np][0]   = b0; bf[2*np+1][0] = b1;
                bf[2*np][1]   = b2; bf[2*np+1][1] = b3;
            }
#pragma unroll
            for (int mf = 0; mf < 2; mf++)
#pragma unroll
                for (int nf = 0; nf < 8; nf++)
                    asm volatile(
                        "mma.sync.aligned.m16n8k16.row.col.f32.f16.f16.f32 "
                        "{%0,%1,%2,%3}, {%4,%5,%6,%7}, {%8,%9}, {%0,%1,%2,%3};\n"
                        : "+f"(acc[mf][nf][0]), "+f"(acc[mf][nf][1]),
                          "+f"(acc[mf][nf][2]), "+f"(acc[mf][nf][3])
                        : "r"(af[mf][0]), "r"(af[mf][1]), "r"(af[mf][2]), "r"(af[mf][3]),
                          "r"(bf[nf][0]), "r"(bf[nf][1]));
        }
    };

    // prologue: 2 stages in flight
    issue(0, 0);
    issue(1, 1);
    for (int t = 0; t < T; t++) {
        if (t + 1 < T) asm volatile("cp.async.wait_group 1;\n");  // stage t arrived
        else           asm volatile("cp.async.wait_group 0;\n");
        __syncthreads();                 // all threads done with buffer (t+2)%3's last read
        if (t + 2 < T) issue(t + 2, (t + 2) % 3);
        compute(t % 3);
    }

    // ---- epilogue ----
#pragma unroll
    for (int mf = 0; mf < 2; mf++) {
        int row = m0 + wm*32 + mf*16 + g;
#pragma unroll
        for (int nf = 0; nf < 8; nf++) {
            int col = n0 + wn*64 + nf*8 + tg*2;
            if (MODE == 0) {
                if (col < N) {
                    C[(size_t)row*N + col]     = acc[mf][nf][0];
                    C[(size_t)(row+8)*N + col] = acc[mf][nf][2];
                }
                if (col + 1 < N) {
                    C[(size_t)row*N + col + 1]     = acc[mf][nf][1];
                    C[(size_t)(row+8)*N + col + 1] = acc[mf][nf][3];
                }
            } else {
                // interleaved GLU: (even,odd) col pair = (z1, z2) for channel d
                int d = col >> 1;
                float b1 = bias[d], b2 = bias[d + DM];
                {
                    float z1 = acc[mf][nf][0] + b1;
                    float z2 = acc[mf][nf][1] + b2;
                    g_x[(size_t)row*DM + d] += z1 / (1.f + expf(-z2));
                }
                {
                    float z1 = acc[mf][nf][2] + b1;
                    float z2 = acc[mf][nf][3] + b2;
                    g_x[(size_t)(row+8)*DM + d] += z1 / (1.f + expf(-z2));
                }
            }
        }
    }
}

// ---------------- final layernorm -> fp16 ----------------
__global__ void __launch_bounds__(128) k_ln(const float* __restrict__ gw,
                                            const float* __restrict__ bw) {
    __shared__ float red[8];
    int m = blockIdx.x, tid = threadIdx.x;
    const float* xr = g_x + (size_t)m*DM;
    float v0 = xr[tid], v1 = xr[tid+128], v2 = xr[tid+256], v3 = xr[tid+384];
    float s = v0+v1+v2+v3;
    float q = v0*v0+v1*v1+v2*v2+v3*v3;
#pragma unroll
    for (int o = 16; o > 0; o >>= 1) {
        s += __shfl_down_sync(0xffffffffu, s, o);
        q += __shfl_down_sync(0xffffffffu, q, o);
    }
    if ((tid & 31) == 0) { red[tid>>5] = s; red[4 + (tid>>5)] = q; }
    __syncthreads();
    if (tid == 0) {
        red[0] = red[0]+red[1]+red[2]+red[3];
        red[4] = red[4]+red[5]+red[6]+red[7];
    }
    __syncthreads();
    float mu  = red[0] * (1.f/DM);
    float var = red[4] * (1.f/DM) - mu*mu;
    float inv = rsqrtf(var + 1e-5f);
    __half* o = g_xh + (size_t)m*DM;
    o[tid]     = __float2half_rn((v0-mu)*inv*gw[tid]     + bw[tid]);
    o[tid+128] = __float2half_rn((v1-mu)*inv*gw[tid+128] + bw[tid+128]);
    o[tid+256] = __float2half_rn((v2-mu)*inv*gw[tid+256] + bw[tid+256]);
    o[tid+384] = __float2half_rn((v3-mu)*inv*gw[tid+384] + bw[tid+384]);
}

// ---------------- host launcher ----------------
extern "C" void kernel_launch(void* const* d_in, const int* in_sizes, int n_in,
                              void* d_out, int out_size) {
    const int*   ids   = (const int*)  d_in[0];
    const float* tok   = (const float*)d_in[1];
    const float* pos   = (const float*)d_in[2];
    const float* logdt = (const float*)d_in[3];
    const float* cre   = (const float*)d_in[4];
    const float* cim   = (const float*)d_in[5];
    const float* skp   = (const float*)d_in[6];
    const float* outw  = (const float*)d_in[7];
    const float* outb  = (const float*)d_in[8];
    const float* lng   = (const float*)d_in[9];
    const float* lnb   = (const float*)d_in[10];
    const float* headw = (const float*)d_in[11];
    float* out = (float*)d_out;

    __half *pyh, *pxh, *pwph, *phwh;
    cudaGetSymbolAddress((void**)&pyh,  g_yh);
    cudaGetSymbolAddress((void**)&pxh,  g_xh);
    cudaGetSymbolAddress((void**)&pwph, g_wph);
    cudaGetSymbolAddress((void**)&phwh, g_hwh);

    cudaFuncSetAttribute(gemm_fp16<0>,
                         cudaFuncAttributeMaxDynamicSharedMemorySize, SMEM_GEMM);
    cudaFuncSetAttribute(gemm_fp16<1>,
                         cudaFuncAttributeMaxDynamicSharedMemorySize, SMEM_GEMM);

    k_detect<<<1, 256>>>(ids);
    k_embed<<<(MROWS*DM)/256, 256>>>(ids, tok, pos);

    // one-shot weight conversion (fp32 -> fp16) + all-layer coefficients
    {
        int n4h = (int)(((size_t)VOCAB*DM) / 4);
        k_cvt<<<(n4h + 255)/256, 256>>>(headw, phwh, n4h);
        int n4p = (NLAYER*D2*DM) / 4;
        k_cvt_proj<<<(n4p + 255)/256, 256>>>(outw, pwph, n4p);
        k_coeff<<<(NLAYER*NM*DM)/256, 256>>>(logdt, cre, cim);
    }

    for (int i = 0; i < NLAYER; i++) {
        k_chunk<<<BATCH*NC*4, 256>>>(i);
        k_scan<<<(BATCH*NM*DM)/256, 256>>>(i);
        k_conv<<<BATCH*NC*4, 256>>>(skp, i);
        dim3 gp(D2/128, MROWS/128);
        gemm_fp16<1><<<gp, 256, SMEM_GEMM>>>(
            pyh, pwph + (size_t)i*D2*DM, outb + (size_t)i*D2, nullptr,
            MROWS, D2, DM);
    }

    k_ln<<<MROWS, 128>>>(lng, lnb);
    dim3 gh((VOCAB + 127)/128, MROWS/128);
    gemm_fp16<0><<<gh, 256, SMEM_GEMM>>>(pxh, phwh, nullptr, out, MROWS, VOCAB, DM);
}

// round 16
// speedup vs baseline: 1.1738x; 1.1738x over previous
#include <cuda_runtime.h>
#include <cuda_fp16.h>
#include <cstdint>

#define BATCH   2
#define LSEQ    2048
#define DM      512
#define NM      32
#define NMH     16          // modes per thread (half)
#define NLAYER  4
#define VOCAB   50257
#define NC      64          // chunks
#define TCH     32          // chunk length = LSEQ/NC
#define D2      (2*DM)
#define MROWS   (BATCH*LSEQ)   // 4096

// ---------------- scratch (device globals; no mallocs allowed) ----------------
__device__ float  g_x   [MROWS*DM];       // residual stream (fp32)
__device__ __half g_yh  [MROWS*DM];       // gelu(conv+skip) output (fp16, GEMM A)
__device__ __half g_xh  [MROWS*DM];       // layernorm output (fp16, GEMM A)
__device__ float  g_sre [BATCH*NC*NM*DM];
__device__ float  g_sim [BATCH*NC*NM*DM];
__device__ float  g_abr [NLAYER*NM*DM];
__device__ float  g_abi [NLAYER*NM*DM];
__device__ float  g_ctr [NLAYER*NM*DM];
__device__ float  g_cti [NLAYER*NM*DM];
__device__ __half g_wph [NLAYER*D2*DM];   // proj weights fp16 (GLU-interleaved rows)
__device__ __half g_hwh [(size_t)VOCAB*DM]; // head weights fp16
__device__ int    g_is64;

// ---------------- input_ids dtype sniffing (int32 vs int64) ----------------
__global__ void k_detect(const int* __restrict__ ids) {
    __shared__ int s_any;
    if (threadIdx.x == 0) s_any = 0;
    __syncthreads();
    int any = 0;
    for (int i = threadIdx.x; i < MROWS/2; i += blockDim.x) any |= ids[2*i + 1];
    if (any) atomicOr(&s_any, 1);
    __syncthreads();
    if (threadIdx.x == 0) g_is64 = (s_any == 0) ? 1 : 0;
}

// ---------------- embedding ----------------
__global__ void k_embed(const int* __restrict__ ids,
                        const float* __restrict__ tok,
                        const float* __restrict__ pos) {
    int idx = blockIdx.x * blockDim.x + threadIdx.x;
    if (idx >= MROWS*DM) return;
    int m = idx / DM, d = idx % DM;
    int l = m % LSEQ;
    int t;
    if (g_is64) t = (int)((const long long*)ids)[m];
    else        t = ids[m];
    g_x[idx] = tok[(size_t)t*DM + d] + pos[l*DM + d];
}

// ---------------- fp32 -> fp16 weight conversion ----------------
__global__ void k_cvt(const float* __restrict__ src, __half* __restrict__ dst, int n4) {
    int i = blockIdx.x * blockDim.x + threadIdx.x;
    if (i >= n4) return;
    float4 v = reinterpret_cast<const float4*>(src)[i];
    reinterpret_cast<__half2*>(dst)[2*i]   = __floats2half2_rn(v.x, v.y);
    reinterpret_cast<__half2*>(dst)[2*i+1] = __floats2half2_rn(v.z, v.w);
}

// proj weights: interleave GLU halves — dst row 2d = src row d, dst row 2d+1 = src row d+512
__global__ void k_cvt_proj(const float* __restrict__ src, __half* __restrict__ dst, int n4) {
    int i = blockIdx.x * blockDim.x + threadIdx.x;   // chunk of 4 floats
    if (i >= n4) return;                             // n4 = NLAYER*D2*(DM/4)
    int k4    = i & 127;                             // DM/4 = 128
    int rem   = i >> 7;
    int row   = rem & (D2 - 1);                      // 0..1023
    int layer = rem >> 10;
    int nrow  = 2*(row & (DM-1)) + (row >> 9);       // interleave
    float4 v = reinterpret_cast<const float4*>(src)[i];
    size_t o = ((size_t)layer*D2 + nrow)*128 + k4;
    reinterpret_cast<__half2*>(dst)[2*o]   = __floats2half2_rn(v.x, v.y);
    reinterpret_cast<__half2*>(dst)[2*o+1] = __floats2half2_rn(v.z, v.w);
}

// ---------------- S4D discretized coefficients (ALL layers upfront) ----------------
__global__ void k_coeff(const float* __restrict__ log_dt,
                        const float* __restrict__ C_re,
                        const float* __restrict__ C_im) {
    int idx = blockIdx.x * blockDim.x + threadIdx.x;   // layer*NM*DM + n*DM + d
    if (idx >= NLAYER*NM*DM) return;
    int d     = idx % DM;
    int n     = (idx / DM) % NM;
    int layer = idx / (NM*DM);
    float dt  = expf(log_dt[layer*DM + d]);
    const float PI = 3.14159265358979f;
    float aim = PI * (float)n;                         // A = -0.5 + i*pi*n
    float xr = -0.5f * dt, xi = aim * dt;
    float e  = expf(xr);
    float abr = e * cosf(xi), abi = e * sinf(xi);      // abar = exp(dt*A)
    float cr = C_re[(layer*DM + d)*NM + n];
    float ci = C_im[(layer*DM + d)*NM + n];
    float emr = abr - 1.0f, emi = abi;                 // exp(dtA)-1
    float nr = cr*emr - ci*emi;
    float ni = cr*emi + ci*emr;
    float inv = 2.0f / (0.25f + aim*aim);
    g_abr[idx] = abr;  g_abi[idx] = abi;
    g_ctr[idx] = (nr*(-0.5f) + ni*aim) * inv;
    g_cti[idx] = (ni*(-0.5f) - nr*aim) * inv;
}

// ---------------- chunk-local end states S_c (16 modes/thread, 256 thr) ----------------
__global__ void __launch_bounds__(256, 3) k_chunk(int layer) {
    int blk = blockIdx.x;                     // b*NC*4 + c*4 + g4
    int g4  = blk & 3;
    int c   = (blk >> 2) % NC;
    int b   = blk / (NC*4);
    int dl  = threadIdx.x & 127;
    int nb  = (threadIdx.x >> 7) * NMH;       // mode base: 0 or 16
    int d   = g4*128 + dl;
    int co  = layer*NM*DM;

    float ar[NMH], ai[NMH], sr[NMH], si[NMH];
#pragma unroll
    for (int n = 0; n < NMH; n++) {
        ar[n] = g_abr[co + (nb+n)*DM + d]; ai[n] = g_abi[co + (nb+n)*DM + d];
        sr[n] = 0.f; si[n] = 0.f;
    }
    const float* xp = g_x + ((size_t)b*LSEQ + c*TCH)*DM + d;

    auto step = [&](float u) {
#pragma unroll
        for (int n = 0; n < NMH; n++) {
            float nsr = fmaf(ar[n], sr[n], fmaf(-ai[n], si[n], u));
            float nsi = fmaf(ar[n], si[n], ai[n]*sr[n]);
            sr[n] = nsr; si[n] = nsi;
        }
    };
    for (int t0 = 0; t0 < TCH; t0 += 4) {       // staged loads: MLP=4
        float u0 = xp[(size_t)(t0+0)*DM];
        float u1 = xp[(size_t)(t0+1)*DM];
        float u2 = xp[(size_t)(t0+2)*DM];
        float u3 = xp[(size_t)(t0+3)*DM];
        step(u0); step(u1); step(u2); step(u3);
    }
    size_t off = ((size_t)(b*NC + c)*NM + nb)*DM + d;
#pragma unroll
    for (int n = 0; n < NMH; n++) {
        g_sre[off + (size_t)n*DM] = sr[n];
        g_sim[off + (size_t)n*DM] = si[n];
    }
}

// ---------------- sequential scan over chunks: S_c -> E_c (prefetched) ----------------
__global__ void k_scan(int layer) {
    int idx = blockIdx.x * blockDim.x + threadIdx.x;
    if (idx >= BATCH*NM*DM) return;
    int d = idx % DM;
    int n = (idx / DM) % NM;
    int b = idx / (NM*DM);
    int co = layer*NM*DM;
    float pr = g_abr[co + n*DM + d], pi = g_abi[co + n*DM + d];
#pragma unroll
    for (int s = 0; s < 5; s++) {              // abar^(2^5) = abar^TCH
        float t = pr*pr - pi*pi; pi = 2.f*pr*pi; pr = t;
    }
    float er = 0.f, ei = 0.f;
    size_t off = ((size_t)(b*NC)*NM + n)*DM + d;
    const size_t stride = (size_t)NM*DM;
    float Sr = g_sre[off], Si = g_sim[off];
    for (int c = 0; c < NC; c++) {
        size_t offn = off + stride;
        float Sr2 = 0.f, Si2 = 0.f;
        if (c + 1 < NC) { Sr2 = g_sre[offn]; Si2 = g_sim[offn]; }  // prefetch
        g_sre[off] = er; g_sim[off] = ei;      // store carry-in E_c
        float ner = fmaf(pr, er, fmaf(-pi, ei, Sr));
        float nei = fmaf(pr, ei, fmaf( pi, er, Si));
        er = ner; ei = nei;
        Sr = Sr2; Si = Si2; off = offn;
    }
}

// ---------------- conv + skip + gelu -> fp16 (16 modes/thread, smem combine) ----------------
__global__ void __launch_bounds__(256, 2) k_conv(const float* __restrict__ skipD, int layer) {
    __shared__ float part[2][TCH][128];
    int blk = blockIdx.x;
    int g4  = blk & 3;
    int c   = (blk >> 2) % NC;
    int b   = blk / (NC*4);
    int dl  = threadIdx.x & 127;
    int h   = threadIdx.x >> 7;               // mode half
    int nb  = h * NMH;
    int d   = g4*128 + dl;
    int co  = layer*NM*DM;

    float ar[NMH], ai[NMH], cr[NMH], ci[NMH], sr[NMH], si[NMH];
    size_t soff = ((size_t)(b*NC + c)*NM + nb)*DM + d;
#pragma unroll
    for (int n = 0; n < NMH; n++) {
        ar[n] = g_abr[co + (nb+n)*DM + d]; ai[n] = g_abi[co + (nb+n)*DM + d];
        cr[n] = g_ctr[co + (nb+n)*DM + d]; ci[n] = g_cti[co + (nb+n)*DM + d];
        sr[n] = g_sre[soff + (size_t)n*DM];
        si[n] = g_sim[soff + (size_t)n*DM];
    }
    const float* xp = g_x + ((size_t)b*LSEQ + c*TCH)*DM + d;

    auto step = [&](float u) -> float {
        float acc = 0.f;
#pragma unroll
        for (int n = 0; n < NMH; n++) {
            float nsr = fmaf(ar[n], sr[n], fmaf(-ai[n], si[n], u));
            float nsi = fmaf(ar[n], si[n], ai[n]*sr[n]);
            sr[n] = nsr; si[n] = nsi;
            acc = fmaf(cr[n], sr[n], acc);
            acc = fmaf(-ci[n], si[n], acc);
        }
        return acc;
    };
    for (int t0 = 0; t0 < TCH; t0 += 4) {       // staged loads: MLP=4
        float u0 = xp[(size_t)(t0+0)*DM];
        float u1 = xp[(size_t)(t0+1)*DM];
        float u2 = xp[(size_t)(t0+2)*DM];
        float u3 = xp[(size_t)(t0+3)*DM];
        part[h][t0+0][dl] = step(u0);
        part[h][t0+1][dl] = step(u1);
        part[h][t0+2][dl] = step(u2);
        part[h][t0+3][dl] = step(u3);
    }
    __syncthreads();

    // finish: 256 threads cover 32t x 128d; skip + gelu + fp16 store
    const float* xb = g_x  + ((size_t)b*LSEQ + c*TCH)*DM + g4*128;
    __half*      yb = g_yh + ((size_t)b*LSEQ + c*TCH)*DM + g4*128;
    for (int i = threadIdx.x; i < TCH*128; i += 256) {
        int t  = i >> 7;
        int dd = i & 127;
        float u  = xb[(size_t)t*DM + dd];
        float sk = skipD[layer*DM + g4*128 + dd];
        float yv = part[0][t][dd] + part[1][t][dd] + sk*u;
        float inner = 0.7978845608028654f * fmaf(0.044715f*yv, yv*yv, yv);
        float gv = 0.5f * yv * (1.f + tanhf(inner));
        yb[(size_t)t*DM + dd] = __float2half_rn(gv);
    }
}

// ---------------- fp16 tensor-core GEMM (m16n8k16, fp32 accum, ldmatrix) ----------------
// C[M,N] = A[M,K] * B[N,K]^T.  128x128 tile, BK=64, 2-stage cp.async (R11 mainloop),
// 8 warps (4m x 2n), warp tile 32x64.
// MODE 0: coalesced smem-staged fp32 store to C with evict-first hint.
// MODE 1: fused GLU (interleaved B) += into g_x.
#define HLDA 72       // smem leading dim in halves (144B stride; 16B-aligned; LDSM conflict-free)
#define STG_H (128*HLDA)             // halves per matrix per stage
#define SMEM_GEMM (2*STG_H*2*2)      // 2 stages x (A+B) x 2B = 73728 (>= 128*129*4 epilogue)

template<int MODE>
__global__ void __launch_bounds__(256, 2) gemm_fp16(
    const __half* __restrict__ A, const __half* __restrict__ Bw,
    const float* __restrict__ bias, float* __restrict__ C,
    int M, int N, int K)
{
    extern __shared__ __half hs[];
    __half* As = hs;              // [2][128*HLDA]
    __half* Bs = hs + 2*STG_H;    // [2][128*HLDA]

    const int tid  = threadIdx.x;
    const int m0   = blockIdx.y * 128;
    const int n0   = blockIdx.x * 128;
    const int warp = tid >> 5, lane = tid & 31;
    const int wm = warp & 3;             // row-warp: wm*32
    const int wn = warp >> 2;            // col-warp: wn*64
    const int g  = lane >> 2;            // 0..7
    const int tg = lane & 3;             // 0..3

    float acc[2][8][4];
#pragma unroll
    for (int i = 0; i < 2; i++)
#pragma unroll
        for (int j = 0; j < 8; j++)
#pragma unroll
            for (int r = 0; r < 4; r++) acc[i][j][r] = 0.f;

    const int lrow = tid >> 1;
    const int lch  = (tid & 1) * 4;     // 16B chunk base (8 chunks per 128B row)

    const __half* Abase = A  + (size_t)m0 * K + lch*8;
    const __half* Bbase = Bw + lch*8;

    const int T = K / 64;               // 8 for K=512

    auto issue = [&](int t, int buf) {
        const __half* Ap = Abase + t*64 + (size_t)lrow * K;
        uint32_t da = (uint32_t)__cvta_generic_to_shared(
                          As + buf*STG_H + lrow*HLDA + lch*8);
#pragma unroll
        for (int c = 0; c < 4; c++)
            asm volatile("cp.async.ca.shared.global [%0], [%1], 16;\n"
                         :: "r"(da + c*16), "l"(Ap + c*8));
        int gr = n0 + lrow;
        const __half* Bp = Bbase + t*64 + (size_t)gr * K;
        uint32_t db = (uint32_t)__cvta_generic_to_shared(
                          Bs + buf*STG_H + lrow*HLDA + lch*8);
        int sz = (gr < N) ? 16 : 0;     // zero-fill OOB rows
#pragma unroll
        for (int c = 0; c < 4; c++)
            asm volatile("cp.async.ca.shared.global [%0], [%1], 16, %2;\n"
                         :: "r"(db + c*16), "l"(Bp + c*8), "r"(sz));
        asm volatile("cp.async.commit_group;\n");
    };

    // ldmatrix lane addressing: lanes 0-15 rows 0-15 @k, lanes 16-31 rows 0-15 @k+8
    const int lm_row = lane & 15;
    const int lm_k   = (lane >> 4) << 3;

    auto compute = [&](int buf) {
        uint32_t abase = (uint32_t)__cvta_generic_to_shared(
            As + buf*STG_H + (wm*32 + lm_row)*HLDA + lm_k);
        uint32_t bbase = (uint32_t)__cvta_generic_to_shared(
            Bs + buf*STG_H + (wn*64 + lm_row)*HLDA + lm_k);
#pragma unroll
        for (int kk = 0; kk < 64; kk += 16) {
            uint32_t af[2][4], bf[8][2];
#pragma unroll
            for (int mf = 0; mf < 2; mf++) {
                uint32_t ad = abase + (mf*16*HLDA + kk)*2;
                asm volatile("ldmatrix.sync.aligned.m8n8.x4.shared.b16 {%0,%1,%2,%3}, [%4];"
                             : "=r"(af[mf][0]), "=r"(af[mf][1]),
                               "=r"(af[mf][2]), "=r"(af[mf][3]) : "r"(ad));
            }
#pragma unroll
            for (int np = 0; np < 4; np++) {
                uint32_t bd = bbase + (np*16*HLDA + kk)*2;
                uint32_t b0, b1, b2, b3;
                asm volatile("ldmatrix.sync.aligned.m8n8.x4.shared.b16 {%0,%1,%2,%3}, [%4];"
                             : "=r"(b0), "=r"(b1), "=r"(b2), "=r"(b3) : "r"(bd));
                bf[2*np][0]   = b0; bf[2*np+1][0] = b1;
                bf[2*np][1]   = b2; bf[2*np+1][1] = b3;
            }
#pragma unroll
            for (int mf = 0; mf < 2; mf++)
#pragma unroll
                for (int nf = 0; nf < 8; nf++)
                    asm volatile(
                        "mma.sync.aligned.m16n8k16.row.col.f32.f16.f16.f32 "
                        "{%0,%1,%2,%3}, {%4,%5,%6,%7}, {%8,%9}, {%0,%1,%2,%3};\n"
                        : "+f"(acc[mf][nf][0]), "+f"(acc[mf][nf][1]),
                          "+f"(acc[mf][nf][2]), "+f"(acc[mf][nf][3])
                        : "r"(af[mf][0]), "r"(af[mf][1]), "r"(af[mf][2]), "r"(af[mf][3]),
                          "r"(bf[nf][0]), "r"(bf[nf][1]));
        }
    };

    issue(0, 0);
    for (int t = 0; t < T; t++) {
        if (t + 1 < T) {
            issue(t + 1, (t + 1) & 1);
            asm volatile("cp.async.wait_group 1;\n");
        } else {
            asm volatile("cp.async.wait_group 0;\n");
        }
        __syncthreads();
        compute(t & 1);
        __syncthreads();
    }

    // ---- epilogue ----
    if (MODE == 0) {
        // stage through smem -> coalesced stores, evict-first (logits never re-read)
        float* fs = reinterpret_cast<float*>(hs);   // [128][129] fp32, 66048 B
#pragma unroll
        for (int mf = 0; mf < 2; mf++) {
            int r = wm*32 + mf*16 + g;
            int c = wn*64 + tg*2;
#pragma unroll
            for (int nf = 0; nf < 8; nf++) {
                fs[(r    )*129 + c + nf*8]     = acc[mf][nf][0];
                fs[(r    )*129 + c + nf*8 + 1] = acc[mf][nf][1];
                fs[(r + 8)*129 + c + nf*8]     = acc[mf][nf][2];
                fs[(r + 8)*129 + c + nf*8 + 1] = acc[mf][nf][3];
            }
        }
        __syncthreads();
        for (int i = tid; i < 128*128; i += 256) {
            int r = i >> 7, c = i & 127;
            int col = n0 + c;
            if (col < N) {
                float v = fs[r*129 + c];
                asm volatile("st.global.cs.f32 [%0], %1;"
                             :: "l"(C + (size_t)(m0 + r)*N + col), "f"(v) : "memory");
            }
        }
    } else {
#pragma unroll
        for (int mf = 0; mf < 2; mf++) {
            int row = m0 + wm*32 + mf*16 + g;
#pragma unroll
            for (int nf = 0; nf < 8; nf++) {
                int col = n0 + wn*64 + nf*8 + tg*2;
                // interleaved GLU: (even,odd) col pair = (z1, z2) for channel d
                int d = col >> 1;
                float b1 = bias[d], b2 = bias[d + DM];
                {
                    float z1 = acc[mf][nf][0] + b1;
                    float z2 = acc[mf][nf][1] + b2;
                    g_x[(size_t)row*DM + d] += z1 / (1.f + expf(-z2));
                }
                {
                    float z1 = acc[mf][nf][2] + b1;
                    float z2 = acc[mf][nf][3] + b2;
                    g_x[(size_t)(row+8)*DM + d] += z1 / (1.f + expf(-z2));
                }
            }
        }
    }
}

// ---------------- final layernorm -> fp16 ----------------
__global__ void __launch_bounds__(128) k_ln(const float* __restrict__ gw,
                                            const float* __restrict__ bw) {
    __shared__ float red[8];
    int m = blockIdx.x, tid = threadIdx.x;
    const float* xr = g_x + (size_t)m*DM;
    float v0 = xr[tid], v1 = xr[tid+128], v2 = xr[tid+256], v3 = xr[tid+384];
    float s = v0+v1+v2+v3;
    float q = v0*v0+v1*v1+v2*v2+v3*v3;
#pragma unroll
    for (int o = 16; o > 0; o >>= 1) {
        s += __shfl_down_sync(0xffffffffu, s, o);
        q += __shfl_down_sync(0xffffffffu, q, o);
    }
    if ((tid & 31) == 0) { red[tid>>5] = s; red[4 + (tid>>5)] = q; }
    __syncthreads();
    if (tid == 0) {
        red[0] = red[0]+red[1]+red[2]+red[3];
        red[4] = red[4]+red[5]+red[6]+red[7];
    }
    __syncthreads();
    float mu  = red[0] * (1.f/DM);
    float var = red[4] * (1.f/DM) - mu*mu;
    float inv = rsqrtf(var + 1e-5f);
    __half* o = g_xh + (size_t)m*DM;
    o[tid]     = __float2half_rn((v0-mu)*inv*gw[tid]     + bw[tid]);
    o[tid+128] = __float2half_rn((v1-mu)*inv*gw[tid+128] + bw[tid+128]);
    o[tid+256] = __float2half_rn((v2-mu)*inv*gw[tid+256] + bw[tid+256]);
    o[tid+384] = __float2half_rn((v3-mu)*inv*gw[tid+384] + bw[tid+384]);
}

// ---------------- host launcher ----------------
extern "C" void kernel_launch(void* const* d_in, const int* in_sizes, int n_in,
                              void* d_out, int out_size) {
    const int*   ids   = (const int*)  d_in[0];
    const float* tok   = (const float*)d_in[1];
    const float* pos   = (const float*)d_in[2];
    const float* logdt = (const float*)d_in[3];
    const float* cre   = (const float*)d_in[4];
    const float* cim   = (const float*)d_in[5];
    const float* skp   = (const float*)d_in[6];
    const float* outw  = (const float*)d_in[7];
    const float* outb  = (const float*)d_in[8];
    const float* lng   = (const float*)d_in[9];
    const float* lnb   = (const float*)d_in[10];
    const float* headw = (const float*)d_in[11];
    float* out = (float*)d_out;

    __half *pyh, *pxh, *pwph, *phwh;
    cudaGetSymbolAddress((void**)&pyh,  g_yh);
    cudaGetSymbolAddress((void**)&pxh,  g_xh);
    cudaGetSymbolAddress((void**)&pwph, g_wph);
    cudaGetSymbolAddress((void**)&phwh, g_hwh);

    cudaFuncSetAttribute(gemm_fp16<0>,
                         cudaFuncAttributeMaxDynamicSharedMemorySize, SMEM_GEMM);
    cudaFuncSetAttribute(gemm_fp16<1>,
                         cudaFuncAttributeMaxDynamicSharedMemorySize, SMEM_GEMM);

    k_detect<<<1, 256>>>(ids);
    k_embed<<<(MROWS*DM)/256, 256>>>(ids, tok, pos);

    // one-shot weight conversion (fp32 -> fp16) + all-layer coefficients
    {
        int n4h = (int)(((size_t)VOCAB*DM) / 4);
        k_cvt<<<(n4h + 255)/256, 256>>>(headw, phwh, n4h);
        int n4p = (NLAYER*D2*DM) / 4;
        k_cvt_proj<<<(n4p + 255)/256, 256>>>(outw, pwph, n4p);
        k_coeff<<<(NLAYER*NM*DM)/256, 256>>>(logdt, cre, cim);
    }

    for (int i = 0; i < NLAYER; i++) {
        k_chunk<<<BATCH*NC*4, 256>>>(i);
        k_scan<<<(BATCH*NM*DM)/256, 256>>>(i);
        k_conv<<<BATCH*NC*4, 256>>>(skp, i);
        dim3 gp(D2/128, MROWS/128);
        gemm_fp16<1><<<gp, 256, SMEM_GEMM>>>(
            pyh, pwph + (size_t)i*D2*DM, outb + (size_t)i*D2, nullptr,
            MROWS, D2, DM);
    }

    k_ln<<<MROWS, 128>>>(lng, lnb);
    dim3 gh((VOCAB + 127)/128, MROWS/128);
    gemm_fp16<0><<<gh, 256, SMEM_GEMM>>>(pxh, phwh, nullptr, out, MROWS, VOCAB, DM);
}